// round 16
// baseline (speedup 1.0000x reference)
#include <cuda_runtime.h>
#include <cuda_bf16.h>
#include <cstdint>
#include <math.h>

// Problem constants
constexpr int NB  = 4;     // batch
constexpr int NN  = 2048;  // nodes
constexpr int IND = 256;   // in_dim
constexpr int NH  = 4;     // heads
constexpr int OD  = 64;    // out_dim per head
constexpr int OUT_ELEMS = NB * NN * IND;
// d_out layout: [out (B,N,H*OD)] then [b_inv (B,H,N,N)]

// Scratch
__device__ float g_gate[(size_t)NB * NN * 256];             // sigmoid gate
__device__ __nv_bfloat16 g_h_hi[(size_t)NB * NN * 256];     // h bf16 hi, [b][k][h*64+o]
__device__ __nv_bfloat16 g_h_lo[(size_t)NB * NN * 256];     // h bf16 lo

// ====================== helpers ======================
__device__ __forceinline__ uint32_t smem_to_u32(const void* p) {
    uint32_t a;
    asm("{ .reg .u64 t; cvta.to.shared.u64 t, %1; cvt.u32.u64 %0, t; }" : "=r"(a) : "l"(p));
    return a;
}
// fp32 pair -> packed bf16x2 hi + bf16x2 lo (round-to-nearest split)
__device__ __forceinline__ void split2(float x0, float x1, uint32_t& hi, uint32_t& lo) {
    __nv_bfloat162 h2 = __floats2bfloat162_rn(x0, x1);
    hi = *reinterpret_cast<uint32_t*>(&h2);
    float f0 = __uint_as_float(hi << 16);
    float f1 = __uint_as_float(hi & 0xFFFF0000u);
    __nv_bfloat162 l2 = __floats2bfloat162_rn(x0 - f0, x1 - f1);
    lo = *reinterpret_cast<uint32_t*>(&l2);
}
__device__ __forceinline__ void ldsm_x4(uint32_t r[4], uint32_t addr) {
    asm volatile("ldmatrix.sync.aligned.m8n8.x4.shared.b16 {%0,%1,%2,%3}, [%4];"
        : "=r"(r[0]), "=r"(r[1]), "=r"(r[2]), "=r"(r[3]) : "r"(addr));
}
__device__ __forceinline__ void ldsm_x4t(uint32_t r[4], uint32_t addr) {
    asm volatile("ldmatrix.sync.aligned.m8n8.x4.trans.shared.b16 {%0,%1,%2,%3}, [%4];"
        : "=r"(r[0]), "=r"(r[1]), "=r"(r[2]), "=r"(r[3]) : "r"(addr));
}
__device__ __forceinline__ void mma_bf16(float c[4], const uint32_t a[4], uint32_t b0, uint32_t b1) {
    asm volatile("mma.sync.aligned.m16n8k16.row.col.f32.bf16.bf16.f32 "
        "{%0,%1,%2,%3}, {%4,%5,%6,%7}, {%8,%9}, {%0,%1,%2,%3};"
        : "+f"(c[0]), "+f"(c[1]), "+f"(c[2]), "+f"(c[3])
        : "r"(a[0]), "r"(a[1]), "r"(a[2]), "r"(a[3]), "r"(b0), "r"(b1));
}
__device__ __forceinline__ void cp_async16(uint32_t dst, const void* src) {
    asm volatile("cp.async.cg.shared.global [%0], [%1], 16;" :: "r"(dst), "l"(src) : "memory");
}
#define CP_COMMIT() asm volatile("cp.async.commit_group;" ::: "memory")
#define CP_WAIT0()  asm volatile("cp.async.wait_group 0;" ::: "memory")
#define SWZ128(b) ((b) ^ (((b) >> 3) & 0x70))
#define SWZ64(b)  ((b) ^ (((b) >> 3) & 0x30))

// =====================================================================
// Kernel 1 (v16): HMMA pre-GEMM  C[8192,512] = feat[8192,256] @ BT^T
//   k_prep FUSED: each CTA builds its 64x256 B^T slice (bf16 hi/lo)
//   directly from Hw/W into PERSISTENT smem (no g_BT, no per-chunk B
//   staging). A double-buffered as in R9. CTA 128x64, 8 warps (32x32),
//   K-chunk 32, single-sync pipeline.
// SMEM: A stages 2x16KB @0 | B persistent 8 chunks x (hi 4KB + lo 4KB) @32KB
// =====================================================================
constexpr int A_STAGE_PRE = 16384;
constexpr int B_BASE_PRE  = 32768;
constexpr int SMEM_PRE = 32768 + 65536 + 128;   // 98.4 KB

__global__ __launch_bounds__(256, 2) void k_pre(
    const float* __restrict__ feat, const float* __restrict__ Hb,
    const float* __restrict__ Hw,   const float* __restrict__ W)
{
    extern __shared__ char dsm_raw[];
    char* sm = (char*)(((uintptr_t)dsm_raw + 127) & ~(uintptr_t)127);
    const uint32_t smu = smem_to_u32(sm);

    const int tid = threadIdx.x;
    const int lane = tid & 31, wid = tid >> 5;
    const int r0 = blockIdx.x * 128;
    const int j0 = blockIdx.y * 64;

    const float* A = feat + (size_t)r0 * IND;

    // ---- B persistent fill: B^T slice rows j0..j0+63, all k ----
    if (j0 < 256) {
        // gate region: row <- Hw[j0+row][k], k-contiguous float4
#pragma unroll
        for (int i = 0; i < 16; i++) {
            const int idx = tid + i * 256;      // 0..4095
            const int row = idx >> 6;
            const int k4  = (idx & 63) << 2;
            float4 v = *(const float4*)&Hw[(size_t)(j0 + row) * IND + k4];
            uint32_t h0, l0, h1, l1;
            split2(v.x, v.y, h0, l0);
            split2(v.z, v.w, h1, l1);
            char* bb = sm + B_BASE_PRE + (k4 >> 5) * 8192;
            const uint32_t off = SWZ64((uint32_t)row * 64 + (uint32_t)(k4 & 31) * 2);
            *(uint2*)(bb + off)        = make_uint2(h0, h1);
            *(uint2*)(bb + 4096 + off) = make_uint2(l0, l1);
        }
    } else {
        // h region: row <- o; B[row][k] = W[h][k][o], o-contiguous loads
        const int h = (j0 - 256) >> 6;
        const int o  = tid & 63;
        const int kg = tid >> 6;                // 0..3 -> k block of 64
        const float* Wb = W + (size_t)h * IND * OD + o;
#pragma unroll
        for (int kk = 0; kk < 64; kk += 2) {
            const int k = kg * 64 + kk;
            float v0 = Wb[(size_t)k * OD];
            float v1 = Wb[(size_t)(k + 1) * OD];
            uint32_t hi, lo;
            split2(v0, v1, hi, lo);
            char* bb = sm + B_BASE_PRE + (k >> 5) * 8192;
            const uint32_t off = SWZ64((uint32_t)o * 64 + (uint32_t)(k & 31) * 2);
            *(uint32_t*)(bb + off)        = hi;
            *(uint32_t*)(bb + 4096 + off) = lo;
        }
    }

    // ---- A staging maps (R9) ----
    const int arow = tid >> 3;           // 0..31, rows arow+32j
    const int acol = (tid & 7) << 2;
    uint32_t saoff[4];
#pragma unroll
    for (int j = 0; j < 4; j++)
        saoff[j] = SWZ64((uint32_t)(arow + 32 * j) * 64 + (uint32_t)acol * 2);

    float4 ar[4];
    float acc[2][4][4];
#pragma unroll
    for (int mi = 0; mi < 2; mi++)
#pragma unroll
        for (int ni = 0; ni < 4; ni++)
#pragma unroll
            for (int r = 0; r < 4; r++) acc[mi][ni][r] = 0.0f;

    const int m_w = (wid >> 1) * 32;
    const int n_w = (wid & 1) * 32;
    const int a_row_l = lane & 15;
    const int a_colb  = ((lane >> 4) << 3) * 2;
    const int b_row_l = (lane & 7) + ((lane >> 4) << 3);
    const int b_kb    = (((lane >> 3) & 1) << 4);

    // ---- prologue: stage A chunk 0, prefetch A chunk 1 ----
#pragma unroll
    for (int j = 0; j < 4; j++)
        ar[j] = *(const float4*)&A[(size_t)(arow + 32 * j) * IND + acol];
    {
        char* buf = sm;
#pragma unroll
        for (int j = 0; j < 4; j++) {
            uint32_t h0, l0, h1, l1;
            split2(ar[j].x, ar[j].y, h0, l0);
            split2(ar[j].z, ar[j].w, h1, l1);
            *(uint2*)(buf + saoff[j])        = make_uint2(h0, h1);
            *(uint2*)(buf + 8192 + saoff[j]) = make_uint2(l0, l1);
        }
    }
#pragma unroll
    for (int j = 0; j < 4; j++)
        ar[j] = *(const float4*)&A[(size_t)(arow + 32 * j) * IND + 32 + acol];

    for (int c = 0; c < 8; c++) {
        __syncthreads();
        // stage A chunk c+1 (overlaps compute(c))
        if (c < 7) {
            char* buf = sm + ((c + 1) & 1) * A_STAGE_PRE;
#pragma unroll
            for (int j = 0; j < 4; j++) {
                uint32_t h0, l0, h1, l1;
                split2(ar[j].x, ar[j].y, h0, l0);
                split2(ar[j].z, ar[j].w, h1, l1);
                *(uint2*)(buf + saoff[j])        = make_uint2(h0, h1);
                *(uint2*)(buf + 8192 + saoff[j]) = make_uint2(l0, l1);
            }
        }
        // prefetch A chunk c+2
        if (c < 6) {
            const int kn = (c + 2) * 32;
#pragma unroll
            for (int j = 0; j < 4; j++)
                ar[j] = *(const float4*)&A[(size_t)(arow + 32 * j) * IND + kn + acol];
        }

        // compute chunk c (B from persistent smem)
        const uint32_t bufa = smu + (c & 1) * A_STAGE_PRE;
        const uint32_t bufb = smu + B_BASE_PRE + c * 8192;
#pragma unroll
        for (int ks = 0; ks < 2; ks++) {
            uint32_t ah[2][4], al[2][4], bhf[2][4], blf[2][4];
#pragma unroll
            for (int mi = 0; mi < 2; mi++) {
                uint32_t sw = SWZ64((uint32_t)(m_w + mi * 16 + a_row_l) * 64 + (uint32_t)(ks * 32) + a_colb);
                ldsm_x4(ah[mi], bufa + sw);
                ldsm_x4(al[mi], bufa + 8192 + sw);
            }
#pragma unroll
            for (int nj = 0; nj < 2; nj++) {
                uint32_t sw = SWZ64((uint32_t)(n_w + nj * 16 + b_row_l) * 64 + (uint32_t)(ks * 32) + b_kb);
                ldsm_x4(bhf[nj], bufb + sw);
                ldsm_x4(blf[nj], bufb + 4096 + sw);
            }
#pragma unroll
            for (int mi = 0; mi < 2; mi++)
#pragma unroll
                for (int ni = 0; ni < 4; ni++) {
                    const int j = ni >> 1, p = (ni & 1) << 1;
                    mma_bf16(acc[mi][ni], ah[mi], bhf[j][p], bhf[j][p + 1]);
                    mma_bf16(acc[mi][ni], ah[mi], blf[j][p], blf[j][p + 1]);
                    mma_bf16(acc[mi][ni], al[mi], bhf[j][p], bhf[j][p + 1]);
                }
        }
    }

    const bool is_gate = (j0 < 256);
#pragma unroll
    for (int mi = 0; mi < 2; mi++) {
#pragma unroll
        for (int rr = 0; rr < 2; rr++) {
            const int m = r0 + m_w + mi * 16 + (lane >> 2) + rr * 8;
#pragma unroll
            for (int ni = 0; ni < 4; ni++) {
                const int j = j0 + n_w + ni * 8 + ((lane & 3) << 1);
                float v0 = acc[mi][ni][rr * 2 + 0];
                float v1 = acc[mi][ni][rr * 2 + 1];
                if (is_gate) {
                    v0 = 1.0f / (1.0f + __expf(-(v0 + __ldg(&Hb[j]))));
                    v1 = 1.0f / (1.0f + __expf(-(v1 + __ldg(&Hb[j + 1]))));
                    *(float2*)&g_gate[(size_t)m * 256 + j] = make_float2(v0, v1);
                } else {
                    uint32_t hi, lo;
                    split2(v0, v1, hi, lo);
                    const size_t off = (size_t)m * 256 + (j - 256);
                    *(uint32_t*)&g_h_hi[off] = hi;
                    *(uint32_t*)&g_h_lo[off] = lo;
                }
            }
        }
    }
}

// =====================================================================
// Kernel 2 (R9-exact + __stcg write-through): HMMA main GEMM per (b,h)
//   512 threads, 16 warps (warp tile 16x32), CTA 128x64, K-chunk 32,
//   2 CTAs/SM, single-sync pipeline, cp.async B, elu/gate epilogue.
// SMEM stage (24KB): A_hi[128][32] 8K | A_lo 8K | B_hi[32][64] 4K | B_lo 4K
// =====================================================================
constexpr int STAGE_M = 24576;
constexpr int SMEM_MAIN = 2 * STAGE_M + 128;

__global__ __launch_bounds__(512, 2) void k_main_mma(
    const float* __restrict__ IB, const float* __restrict__ feat,
    const float* __restrict__ bias, float* __restrict__ out)
{
    extern __shared__ char dsm_raw[];
    char* sm = (char*)(((uintptr_t)dsm_raw + 127) & ~(uintptr_t)127);
    const uint32_t smu = smem_to_u32(sm);

    const int tid = threadIdx.x;
    const int lane = tid & 31, wid = tid >> 5;
    const int r0 = blockIdx.x * 128;
    const int bh = blockIdx.y, bb = bh >> 2, hh = bh & 3;

    const float* A   = IB + (size_t)bh * NN * NN + (size_t)r0 * NN;
    float* Acopy     = out + OUT_ELEMS + (size_t)bh * NN * NN + (size_t)r0 * NN;

    // A staging: 2 float4 per thread (rows arow, arow+64)
    const int arow = tid >> 3;           // 0..63
    const int acol = (tid & 7) << 2;     // fp32 col 0..28
    uint32_t saoff[2];
#pragma unroll
    for (int j = 0; j < 2; j++)
        saoff[j] = SWZ64((uint32_t)(arow + 64 * j) * 64 + (uint32_t)acol * 2);

    // B staging: tids 0..255 stage hi, 256..511 stage lo (16B each)
    const int bu   = tid & 255;
    const int brow = bu >> 3;            // 0..31 (k rows)
    const int bcol = (bu & 7) << 3;      // bf16 o col base (16B)
    const int bsel = tid >> 8;           // 0 = hi, 1 = lo
    const uint32_t sbdst = 16384 + (uint32_t)bsel * 4096 + SWZ128((uint32_t)brow * 128 + (uint32_t)bcol * 2);
    const __nv_bfloat16* BS = (bsel ? g_h_lo : g_h_hi) + ((size_t)bb * NN + brow) * 256 + hh * 64 + bcol;

    float4 ar[2];
    float acc[4][4];
#pragma unroll
    for (int ni = 0; ni < 4; ni++)
#pragma unroll
        for (int r = 0; r < 4; r++) acc[ni][r] = 0.0f;

    const int m_w = (wid >> 1) * 16;     // 8 M-slices of 16 rows
    const int n_w = (wid & 1) * 32;      // 2 N-slices of 32
    const int a_row_l = lane & 15;
    const int a_colb  = ((lane >> 4) << 3) * 2;
    const int b_krow  = (lane & 7) + ((lane >> 3) & 1) * 8;
    const int b_ncol  = (lane >> 4) << 3;

    // ---- prologue: stage chunk 0, prefetch A chunk 1 ----
#pragma unroll
    for (int j = 0; j < 2; j++)
        ar[j] = *(const float4*)&A[(size_t)(arow + 64 * j) * NN + acol];
    {
        char* buf = sm;
        cp_async16(smu + sbdst, BS);
        CP_COMMIT();
#pragma unroll
        for (int j = 0; j < 2; j++) {
            __stcg((float4*)&Acopy[(size_t)(arow + 64 * j) * NN + acol], ar[j]);
            uint32_t h0, l0, h1, l1;
            split2(ar[j].x, ar[j].y, h0, l0);
            split2(ar[j].z, ar[j].w, h1, l1);
            *(uint2*)(buf + saoff[j])        = make_uint2(h0, h1);
            *(uint2*)(buf + 8192 + saoff[j]) = make_uint2(l0, l1);
        }
        CP_WAIT0();
    }
#pragma unroll
    for (int j = 0; j < 2; j++)
        ar[j] = *(const float4*)&A[(size_t)(arow + 64 * j) * NN + 32 + acol];

    for (int c = 0; c < 64; c++) {
        __syncthreads();

        // stage chunk c+1 — overlaps compute(c)
        if (c < 63) {
            char* buf = sm + ((c + 1) & 1) * STAGE_M;
            const uint32_t bufn = smu + ((c + 1) & 1) * STAGE_M;
            const int k1 = (c + 1) * 32;
            cp_async16(bufn + sbdst, BS + (size_t)k1 * 256);
            CP_COMMIT();
#pragma unroll
            for (int j = 0; j < 2; j++) {
                __stcg((float4*)&Acopy[(size_t)(arow + 64 * j) * NN + k1 + acol], ar[j]);
                uint32_t h0, l0, h1, l1;
                split2(ar[j].x, ar[j].y, h0, l0);
                split2(ar[j].z, ar[j].w, h1, l1);
                *(uint2*)(buf + saoff[j])        = make_uint2(h0, h1);
                *(uint2*)(buf + 8192 + saoff[j]) = make_uint2(l0, l1);
            }
        }
        // prefetch A chunk c+2
        if (c < 62) {
            const int kn = (c + 2) * 32;
#pragma unroll
            for (int j = 0; j < 2; j++)
                ar[j] = *(const float4*)&A[(size_t)(arow + 64 * j) * NN + kn + acol];
        }

        // compute chunk c (warp tile 16x32)
        const uint32_t bufu = smu + (c & 1) * STAGE_M;
#pragma unroll
        for (int ks = 0; ks < 2; ks++) {
            uint32_t ah[4], al[4], bhf[2][4], blf[2][4];
            {
                uint32_t sw = SWZ64((uint32_t)(m_w + a_row_l) * 64 + (uint32_t)(ks * 32) + a_colb);
                ldsm_x4(ah, bufu + sw);
                ldsm_x4(al, bufu + 8192 + sw);
            }
#pragma unroll
            for (int nj = 0; nj < 2; nj++) {
                uint32_t sw = SWZ128((uint32_t)(ks * 16 + b_krow) * 128 + (uint32_t)(n_w + nj * 16 + b_ncol) * 2);
                ldsm_x4t(bhf[nj], bufu + 16384 + sw);
                ldsm_x4t(blf[nj], bufu + 20480 + sw);
            }
#pragma unroll
            for (int ni = 0; ni < 4; ni++) {
                const int j = ni >> 1, p = (ni & 1) << 1;
                mma_bf16(acc[ni], ah, bhf[j][p], bhf[j][p + 1]);
                mma_bf16(acc[ni], ah, blf[j][p], blf[j][p + 1]);
                mma_bf16(acc[ni], al, bhf[j][p], bhf[j][p + 1]);
            }
        }
        CP_WAIT0();
    }

    // epilogue: bias + elu + sigmoid-gate blend (16 rows x 32 cols per warp)
#pragma unroll
    for (int rr = 0; rr < 2; rr++) {
        const int nrow = r0 + m_w + (lane >> 2) + rr * 8;
        const size_t row = (size_t)bb * NN + nrow;
#pragma unroll
        for (int ni = 0; ni < 4; ni++) {
            const int col = n_w + ni * 8 + ((lane & 3) << 1);
            const int cg = hh * 64 + col;
            float v0 = acc[ni][rr * 2 + 0] + __ldg(&bias[col]);
            float v1 = acc[ni][rr * 2 + 1] + __ldg(&bias[col + 1]);
            float e0 = (v0 > 0.0f) ? v0 : expm1f(v0);
            float e1 = (v1 > 0.0f) ? v1 : expm1f(v1);
            float2 g2 = *(const float2*)&g_gate[row * 256 + cg];
            float2 f2 = *(const float2*)&feat[row * IND + cg];
            float2 o2;
            o2.x = g2.x * e0 + (1.0f - g2.x) * f2.x;
            o2.y = g2.y * e1 + (1.0f - g2.y) * f2.y;
            *(float2*)&out[row * IND + cg] = o2;
        }
    }
}

extern "C" void kernel_launch(void* const* d_in, const int* in_sizes, int n_in,
                              void* d_out, int out_size)
{
    const float* feat = (const float*)d_in[0];  // [4,2048,256]
    const float* IB   = (const float*)d_in[1];  // [4,4,2048,2048]
    const float* W    = (const float*)d_in[2];  // [4,256,64]
    const float* bias = (const float*)d_in[3];  // [64]
    const float* Hw   = (const float*)d_in[4];  // [256,256]
    const float* Hb   = (const float*)d_in[5];  // [256]
    float* out = (float*)d_out;

    // Kernel 1: gate + h (HMMA) with fused B^T build (k_prep eliminated)
    cudaFuncSetAttribute(k_pre, cudaFuncAttributeMaxDynamicSharedMemorySize, SMEM_PRE);
    dim3 g1(NB * NN / 128, 512 / 64);
    k_pre<<<g1, 256, SMEM_PRE>>>(feat, Hb, Hw, W);

    // Kernel 2: HMMA main GEMM (R9-exact, stcg write-through) + epilogue
    cudaFuncSetAttribute(k_main_mma, cudaFuncAttributeMaxDynamicSharedMemorySize, SMEM_MAIN);
    dim3 g2(NN / 128, NB * NH);
    k_main_mma<<<g2, 512, SMEM_MAIN>>>(IB, feat, bias, out);
}

// round 17
// speedup vs baseline: 1.0092x; 1.0092x over previous
#include <cuda_runtime.h>
#include <cuda_bf16.h>
#include <cstdint>
#include <math.h>

// Problem constants
constexpr int NB  = 4;     // batch
constexpr int NN  = 2048;  // nodes
constexpr int IND = 256;   // in_dim
constexpr int NH  = 4;     // heads
constexpr int OD  = 64;    // out_dim per head
constexpr int OUT_ELEMS = NB * NN * IND;
// d_out layout: [out (B,N,H*OD)] then [b_inv (B,H,N,N)]

// Scratch
__device__ float g_gate[(size_t)NB * NN * 256];             // sigmoid gate
__device__ __nv_bfloat16 g_h_hi[(size_t)NB * NN * 256];     // h bf16 hi, [b][k][h*64+o]
__device__ __nv_bfloat16 g_h_lo[(size_t)NB * NN * 256];     // h bf16 lo
__device__ __nv_bfloat16 g_BT_hi[512 * IND];                // B^T for k_pre: [j][k]
__device__ __nv_bfloat16 g_BT_lo[512 * IND];

// ====================== helpers ======================
__device__ __forceinline__ uint32_t smem_to_u32(const void* p) {
    uint32_t a;
    asm("{ .reg .u64 t; cvta.to.shared.u64 t, %1; cvt.u32.u64 %0, t; }" : "=r"(a) : "l"(p));
    return a;
}
// fp32 pair -> packed bf16x2 hi + bf16x2 lo (round-to-nearest split)
__device__ __forceinline__ void split2(float x0, float x1, uint32_t& hi, uint32_t& lo) {
    __nv_bfloat162 h2 = __floats2bfloat162_rn(x0, x1);
    hi = *reinterpret_cast<uint32_t*>(&h2);
    float f0 = __uint_as_float(hi << 16);
    float f1 = __uint_as_float(hi & 0xFFFF0000u);
    __nv_bfloat162 l2 = __floats2bfloat162_rn(x0 - f0, x1 - f1);
    lo = *reinterpret_cast<uint32_t*>(&l2);
}
__device__ __forceinline__ void ldsm_x4(uint32_t r[4], uint32_t addr) {
    asm volatile("ldmatrix.sync.aligned.m8n8.x4.shared.b16 {%0,%1,%2,%3}, [%4];"
        : "=r"(r[0]), "=r"(r[1]), "=r"(r[2]), "=r"(r[3]) : "r"(addr));
}
__device__ __forceinline__ void ldsm_x4t(uint32_t r[4], uint32_t addr) {
    asm volatile("ldmatrix.sync.aligned.m8n8.x4.trans.shared.b16 {%0,%1,%2,%3}, [%4];"
        : "=r"(r[0]), "=r"(r[1]), "=r"(r[2]), "=r"(r[3]) : "r"(addr));
}
__device__ __forceinline__ void mma_bf16(float c[4], const uint32_t a[4], uint32_t b0, uint32_t b1) {
    asm volatile("mma.sync.aligned.m16n8k16.row.col.f32.bf16.bf16.f32 "
        "{%0,%1,%2,%3}, {%4,%5,%6,%7}, {%8,%9}, {%0,%1,%2,%3};"
        : "+f"(c[0]), "+f"(c[1]), "+f"(c[2]), "+f"(c[3])
        : "r"(a[0]), "r"(a[1]), "r"(a[2]), "r"(a[3]), "r"(b0), "r"(b1));
}
__device__ __forceinline__ void cp_async16(uint32_t dst, const void* src) {
    asm volatile("cp.async.cg.shared.global [%0], [%1], 16;" :: "r"(dst), "l"(src) : "memory");
}
#define CP_COMMIT() asm volatile("cp.async.commit_group;" ::: "memory")
#define CP_WAIT0()  asm volatile("cp.async.wait_group 0;" ::: "memory")
#define CP_WAIT1()  asm volatile("cp.async.wait_group 1;" ::: "memory")
#define SWZ128(b) ((b) ^ (((b) >> 3) & 0x70))
#define SWZ64(b)  ((b) ^ (((b) >> 3) & 0x30))

// =====================================================================
// Prep: build B^T (bf16 hi/lo) for k_pre.  j<256: Hw[j][k]; j>=256: W[h][k][o]
// =====================================================================
__global__ __launch_bounds__(256) void k_prep(const float* __restrict__ Hw, const float* __restrict__ W)
{
    const int item = blockIdx.x * 256 + threadIdx.x;   // 0..32767
    if (item < 16384) {
        const int j  = item >> 6;
        const int k4 = (item & 63) << 2;
        float4 v = *(const float4*)&Hw[(size_t)j * IND + k4];
        uint32_t h0, l0, h1, l1;
        split2(v.x, v.y, h0, l0);
        split2(v.z, v.w, h1, l1);
        *(uint2*)&g_BT_hi[(size_t)j * IND + k4] = make_uint2(h0, h1);
        *(uint2*)&g_BT_lo[(size_t)j * IND + k4] = make_uint2(l0, l1);
    } else {
        const int it  = item - 16384;
        const int h   = it >> 12;
        const int idx = it & 4095;
        const int o   = idx & 63;
        const int k4  = (idx >> 6) << 2;
        const float* Wb = W + ((size_t)h * IND + k4) * OD + o;
        float v0 = Wb[0 * OD];
        float v1 = Wb[1 * OD];
        float v2 = Wb[2 * OD];
        float v3 = Wb[3 * OD];
        uint32_t h0, l0, h1, l1;
        split2(v0, v1, h0, l0);
        split2(v2, v3, h1, l1);
        const int j = 256 + h * 64 + o;
        *(uint2*)&g_BT_hi[(size_t)j * IND + k4] = make_uint2(h0, h1);
        *(uint2*)&g_BT_lo[(size_t)j * IND + k4] = make_uint2(l0, l1);
    }
}

// =====================================================================
// Kernel 1 (R15-exact): HMMA pre-GEMM  C[8192,512] = feat @ BT^T
//   CTA 128x64, 8 warps (32x32), K-chunk 32, single-sync pipeline,
//   cp.async B (bf16 in g_BT).
// =====================================================================
constexpr int STAGE_PRE = 24576;
constexpr int SMEM_PRE = 2 * STAGE_PRE + 128;

__global__ __launch_bounds__(256, 2) void k_pre(
    const float* __restrict__ feat, const float* __restrict__ Hb)
{
    extern __shared__ char dsm_raw[];
    char* sm = (char*)(((uintptr_t)dsm_raw + 127) & ~(uintptr_t)127);
    const uint32_t smu = smem_to_u32(sm);

    const int tid = threadIdx.x;
    const int lane = tid & 31, wid = tid >> 5;
    const int r0 = blockIdx.x * 128;
    const int j0 = blockIdx.y * 64;

    const float* A = feat + (size_t)r0 * IND;

    const int arow = tid >> 3;
    const int acol = (tid & 7) << 2;
    const int brow = tid >> 2;
    const int bk8  = (tid & 3) << 3;

    uint32_t saoff[4];
#pragma unroll
    for (int j = 0; j < 4; j++)
        saoff[j] = SWZ64((uint32_t)(arow + 32 * j) * 64 + (uint32_t)acol * 2);
    const uint32_t sboff = SWZ64((uint32_t)brow * 64 + (uint32_t)bk8 * 2);

    const __nv_bfloat16* BhS = g_BT_hi + (size_t)(j0 + brow) * IND + bk8;
    const __nv_bfloat16* BlS = g_BT_lo + (size_t)(j0 + brow) * IND + bk8;

    float4 ar[4];
    float acc[2][4][4];
#pragma unroll
    for (int mi = 0; mi < 2; mi++)
#pragma unroll
        for (int ni = 0; ni < 4; ni++)
#pragma unroll
            for (int r = 0; r < 4; r++) acc[mi][ni][r] = 0.0f;

    const int m_w = (wid >> 1) * 32;
    const int n_w = (wid & 1) * 32;
    const int a_row_l = lane & 15;
    const int a_colb  = ((lane >> 4) << 3) * 2;
    const int b_row_l = (lane & 7) + ((lane >> 4) << 3);
    const int b_kb    = (((lane >> 3) & 1) << 4);

#pragma unroll
    for (int j = 0; j < 4; j++)
        ar[j] = *(const float4*)&A[(size_t)(arow + 32 * j) * IND + acol];
    {
        char* buf = sm;
#pragma unroll
        for (int j = 0; j < 4; j++) {
            uint32_t h0, l0, h1, l1;
            split2(ar[j].x, ar[j].y, h0, l0);
            split2(ar[j].z, ar[j].w, h1, l1);
            *(uint2*)(buf + saoff[j])        = make_uint2(h0, h1);
            *(uint2*)(buf + 8192 + saoff[j]) = make_uint2(l0, l1);
        }
        cp_async16(smu + 16384 + sboff, BhS);
        cp_async16(smu + 20480 + sboff, BlS);
        CP_COMMIT();
        CP_WAIT0();
    }
#pragma unroll
    for (int j = 0; j < 4; j++)
        ar[j] = *(const float4*)&A[(size_t)(arow + 32 * j) * IND + 32 + acol];

    for (int c = 0; c < 8; c++) {
        __syncthreads();
        if (c < 7) {
            char* buf = sm + ((c + 1) & 1) * STAGE_PRE;
            const uint32_t bufn = smu + ((c + 1) & 1) * STAGE_PRE;
            cp_async16(bufn + 16384 + sboff, BhS + (c + 1) * 32);
            cp_async16(bufn + 20480 + sboff, BlS + (c + 1) * 32);
            CP_COMMIT();
#pragma unroll
            for (int j = 0; j < 4; j++) {
                uint32_t h0, l0, h1, l1;
                split2(ar[j].x, ar[j].y, h0, l0);
                split2(ar[j].z, ar[j].w, h1, l1);
                *(uint2*)(buf + saoff[j])        = make_uint2(h0, h1);
                *(uint2*)(buf + 8192 + saoff[j]) = make_uint2(l0, l1);
            }
        }
        if (c < 6) {
            const int kn = (c + 2) * 32;
#pragma unroll
            for (int j = 0; j < 4; j++)
                ar[j] = *(const float4*)&A[(size_t)(arow + 32 * j) * IND + kn + acol];
        }

        const uint32_t bufu = smu + (c & 1) * STAGE_PRE;
#pragma unroll
        for (int ks = 0; ks < 2; ks++) {
            uint32_t ah[2][4], al[2][4], bhf[2][4], blf[2][4];
#pragma unroll
            for (int mi = 0; mi < 2; mi++) {
                uint32_t sw = SWZ64((uint32_t)(m_w + mi * 16 + a_row_l) * 64 + (uint32_t)(ks * 32) + a_colb);
                ldsm_x4(ah[mi], bufu + sw);
                ldsm_x4(al[mi], bufu + 8192 + sw);
            }
#pragma unroll
            for (int nj = 0; nj < 2; nj++) {
                uint32_t sw = SWZ64((uint32_t)(n_w + nj * 16 + b_row_l) * 64 + (uint32_t)(ks * 32) + b_kb);
                ldsm_x4(bhf[nj], bufu + 16384 + sw);
                ldsm_x4(blf[nj], bufu + 20480 + sw);
            }
#pragma unroll
            for (int mi = 0; mi < 2; mi++)
#pragma unroll
                for (int ni = 0; ni < 4; ni++) {
                    const int j = ni >> 1, p = (ni & 1) << 1;
                    mma_bf16(acc[mi][ni], ah[mi], bhf[j][p], bhf[j][p + 1]);
                    mma_bf16(acc[mi][ni], ah[mi], blf[j][p], blf[j][p + 1]);
                    mma_bf16(acc[mi][ni], al[mi], bhf[j][p], bhf[j][p + 1]);
                }
        }
        CP_WAIT0();
    }

    const bool is_gate = (j0 < 256);
#pragma unroll
    for (int mi = 0; mi < 2; mi++) {
#pragma unroll
        for (int rr = 0; rr < 2; rr++) {
            const int m = r0 + m_w + mi * 16 + (lane >> 2) + rr * 8;
#pragma unroll
            for (int ni = 0; ni < 4; ni++) {
                const int j = j0 + n_w + ni * 8 + ((lane & 3) << 1);
                float v0 = acc[mi][ni][rr * 2 + 0];
                float v1 = acc[mi][ni][rr * 2 + 1];
                if (is_gate) {
                    v0 = 1.0f / (1.0f + __expf(-(v0 + __ldg(&Hb[j]))));
                    v1 = 1.0f / (1.0f + __expf(-(v1 + __ldg(&Hb[j + 1]))));
                    *(float2*)&g_gate[(size_t)m * 256 + j] = make_float2(v0, v1);
                } else {
                    uint32_t hi, lo;
                    split2(v0, v1, hi, lo);
                    const size_t off = (size_t)m * 256 + (j - 256);
                    *(uint32_t*)&g_h_hi[off] = hi;
                    *(uint32_t*)&g_h_lo[off] = lo;
                }
            }
        }
    }
}

// =====================================================================
// Kernel 2 (R9 + 3-stage B ring): HMMA main GEMM per (b,h)
//   512 threads, 16 warps (warp tile 16x32), CTA 128x64, K-chunk 32,
//   2 CTAs/SM. A double-buffered (reg->split->STS), B in a 3-buffer
//   cp.async ring with prefetch distance 2 (wait_group 1): each B fetch
//   gets 2 full iterations; barrier arrival no longer gated on the
//   just-issued group. IB write-through fused, elu/gate epilogue.
// SMEM: A 2x16KB @0 | B ring 3x8KB @32768  (56.4KB/CTA)
// =====================================================================
constexpr int A_STAGE_M = 16384;
constexpr int B_BASE_M  = 32768;
constexpr int SMEM_MAIN = 32768 + 3 * 8192 + 128;

__global__ __launch_bounds__(512, 2) void k_main_mma(
    const float* __restrict__ IB, const float* __restrict__ feat,
    const float* __restrict__ bias, float* __restrict__ out)
{
    extern __shared__ char dsm_raw[];
    char* sm = (char*)(((uintptr_t)dsm_raw + 127) & ~(uintptr_t)127);
    const uint32_t smu = smem_to_u32(sm);

    const int tid = threadIdx.x;
    const int lane = tid & 31, wid = tid >> 5;
    const int r0 = blockIdx.x * 128;
    const int bh = blockIdx.y, bb = bh >> 2, hh = bh & 3;

    const float* A   = IB + (size_t)bh * NN * NN + (size_t)r0 * NN;
    float* Acopy     = out + OUT_ELEMS + (size_t)bh * NN * NN + (size_t)r0 * NN;

    // A staging: 2 float4 per thread (rows arow, arow+64)
    const int arow = tid >> 3;           // 0..63
    const int acol = (tid & 7) << 2;     // fp32 col 0..28
    uint32_t saoff[2];
#pragma unroll
    for (int j = 0; j < 2; j++)
        saoff[j] = SWZ64((uint32_t)(arow + 64 * j) * 64 + (uint32_t)acol * 2);

    // B staging: tids 0..255 stage hi, 256..511 stage lo (16B each)
    const int bu   = tid & 255;
    const int brow = bu >> 3;            // 0..31 (k rows)
    const int bcol = (bu & 7) << 3;      // bf16 o col base (16B)
    const int bsel = tid >> 8;           // 0 = hi, 1 = lo
    const uint32_t sb_off = (uint32_t)bsel * 4096 + SWZ128((uint32_t)brow * 128 + (uint32_t)bcol * 2);
    const __nv_bfloat16* BS = (bsel ? g_h_lo : g_h_hi) + ((size_t)bb * NN + brow) * 256 + hh * 64 + bcol;

    float4 ar[2];
    float acc[4][4];
#pragma unroll
    for (int ni = 0; ni < 4; ni++)
#pragma unroll
        for (int r = 0; r < 4; r++) acc[ni][r] = 0.0f;

    const int m_w = (wid >> 1) * 16;     // 8 M-slices of 16 rows
    const int n_w = (wid & 1) * 32;      // 2 N-slices of 32
    const int a_row_l = lane & 15;
    const int a_colb  = ((lane >> 4) << 3) * 2;
    const int b_krow  = (lane & 7) + ((lane >> 3) & 1) * 8;
    const int b_ncol  = (lane >> 4) << 3;

    // ---- prologue: issue B(0), B(1); stage A chunk 0; prefetch A chunk 1 ----
    cp_async16(smu + B_BASE_M + 0 * 8192 + sb_off, BS);
    CP_COMMIT();
    cp_async16(smu + B_BASE_M + 1 * 8192 + sb_off, BS + (size_t)32 * 256);
    CP_COMMIT();

#pragma unroll
    for (int j = 0; j < 2; j++)
        ar[j] = *(const float4*)&A[(size_t)(arow + 64 * j) * NN + acol];
    {
        char* buf = sm;
#pragma unroll
        for (int j = 0; j < 2; j++) {
            *(float4*)&Acopy[(size_t)(arow + 64 * j) * NN + acol] = ar[j];
            uint32_t h0, l0, h1, l1;
            split2(ar[j].x, ar[j].y, h0, l0);
            split2(ar[j].z, ar[j].w, h1, l1);
            *(uint2*)(buf + saoff[j])        = make_uint2(h0, h1);
            *(uint2*)(buf + 8192 + saoff[j]) = make_uint2(l0, l1);
        }
    }
#pragma unroll
    for (int j = 0; j < 2; j++)
        ar[j] = *(const float4*)&A[(size_t)(arow + 64 * j) * NN + 32 + acol];

    int bring = 0;   // ring index of chunk c
    for (int c = 0; c < 64; c++) {
        // B(c) must be complete: at most 1 newer group may remain pending
        if (c < 62) CP_WAIT1(); else CP_WAIT0();
        __syncthreads();

        // issue B(c+2) into ring slot (c+2)%3 (freed: consumed at c-1)
        if (c < 62) {
            int rn = bring + 2; if (rn >= 3) rn -= 3;
            cp_async16(smu + B_BASE_M + (uint32_t)rn * 8192 + sb_off,
                       BS + (size_t)(c + 2) * 32 * 256);
            CP_COMMIT();
        }

        // stage A chunk c+1 (write-through STG + split STS) — overlaps compute(c)
        if (c < 63) {
            char* buf = sm + ((c + 1) & 1) * A_STAGE_M;
            const int k1 = (c + 1) * 32;
#pragma unroll
            for (int j = 0; j < 2; j++) {
                *(float4*)&Acopy[(size_t)(arow + 64 * j) * NN + k1 + acol] = ar[j];
                uint32_t h0, l0, h1, l1;
                split2(ar[j].x, ar[j].y, h0, l0);
                split2(ar[j].z, ar[j].w, h1, l1);
                *(uint2*)(buf + saoff[j])        = make_uint2(h0, h1);
                *(uint2*)(buf + 8192 + saoff[j]) = make_uint2(l0, l1);
            }
        }
        // prefetch A chunk c+2
        if (c < 62) {
            const int kn = (c + 2) * 32;
#pragma unroll
            for (int j = 0; j < 2; j++)
                ar[j] = *(const float4*)&A[(size_t)(arow + 64 * j) * NN + kn + acol];
        }

        // compute chunk c (warp tile 16x32; B from ring slot bring)
        const uint32_t bufa = smu + (c & 1) * A_STAGE_M;
        const uint32_t bufb = smu + B_BASE_M + (uint32_t)bring * 8192;
#pragma unroll
        for (int ks = 0; ks < 2; ks++) {
            uint32_t ah[4], al[4], bhf[2][4], blf[2][4];
            {
                uint32_t sw = SWZ64((uint32_t)(m_w + a_row_l) * 64 + (uint32_t)(ks * 32) + a_colb);
                ldsm_x4(ah, bufa + sw);
                ldsm_x4(al, bufa + 8192 + sw);
            }
#pragma unroll
            for (int nj = 0; nj < 2; nj++) {
                uint32_t sw = SWZ128((uint32_t)(ks * 16 + b_krow) * 128 + (uint32_t)(n_w + nj * 16 + b_ncol) * 2);
                ldsm_x4t(bhf[nj], bufb + sw);
                ldsm_x4t(blf[nj], bufb + 4096 + sw);
            }
#pragma unroll
            for (int ni = 0; ni < 4; ni++) {
                const int j = ni >> 1, p = (ni & 1) << 1;
                mma_bf16(acc[ni], ah, bhf[j][p], bhf[j][p + 1]);
                mma_bf16(acc[ni], ah, blf[j][p], blf[j][p + 1]);
                mma_bf16(acc[ni], al, bhf[j][p], bhf[j][p + 1]);
            }
        }
        bring++; if (bring >= 3) bring -= 3;
    }

    // epilogue: bias + elu + sigmoid-gate blend (16 rows x 32 cols per warp)
#pragma unroll
    for (int rr = 0; rr < 2; rr++) {
        const int nrow = r0 + m_w + (lane >> 2) + rr * 8;
        const size_t row = (size_t)bb * NN + nrow;
#pragma unroll
        for (int ni = 0; ni < 4; ni++) {
            const int col = n_w + ni * 8 + ((lane & 3) << 1);
            const int cg = hh * 64 + col;
            float v0 = acc[ni][rr * 2 + 0] + __ldg(&bias[col]);
            float v1 = acc[ni][rr * 2 + 1] + __ldg(&bias[col + 1]);
            float e0 = (v0 > 0.0f) ? v0 : expm1f(v0);
            float e1 = (v1 > 0.0f) ? v1 : expm1f(v1);
            float2 g2 = *(const float2*)&g_gate[row * 256 + cg];
            float2 f2 = *(const float2*)&feat[row * IND + cg];
            float2 o2;
            o2.x = g2.x * e0 + (1.0f - g2.x) * f2.x;
            o2.y = g2.y * e1 + (1.0f - g2.y) * f2.y;
            *(float2*)&out[row * IND + cg] = o2;
        }
    }
}

extern "C" void kernel_launch(void* const* d_in, const int* in_sizes, int n_in,
                              void* d_out, int out_size)
{
    const float* feat = (const float*)d_in[0];  // [4,2048,256]
    const float* IB   = (const float*)d_in[1];  // [4,4,2048,2048]
    const float* W    = (const float*)d_in[2];  // [4,256,64]
    const float* bias = (const float*)d_in[3];  // [64]
    const float* Hw   = (const float*)d_in[4];  // [256,256]
    const float* Hb   = (const float*)d_in[5];  // [256]
    float* out = (float*)d_out;

    // Prep: bf16 hi/lo B^T for k_pre (coalesced W path)
    k_prep<<<128, 256>>>(Hw, W);

    // Kernel 1: gate + h (HMMA, R15-exact)
    cudaFuncSetAttribute(k_pre, cudaFuncAttributeMaxDynamicSharedMemorySize, SMEM_PRE);
    dim3 g1(NB * NN / 128, 512 / 64);
    k_pre<<<g1, 256, SMEM_PRE>>>(feat, Hb);

    // Kernel 2: HMMA main GEMM (R9 + 3-stage B ring) + IB copy + epilogue
    cudaFuncSetAttribute(k_main_mma, cudaFuncAttributeMaxDynamicSharedMemorySize, SMEM_MAIN);
    dim3 g2(NN / 128, NB * NH);
    k_main_mma<<<g2, 512, SMEM_MAIN>>>(IB, feat, bias, out);
}